// round 6
// baseline (speedup 1.0000x reference)
#include <cuda_runtime.h>
#include <cstdint>
#include <math.h>

// Shapes (fixed by the problem)
#define LL   1024
#define BSZ  4
#define DD   1024
#define NHH  16
#define DHH  64
#define PD   2048          // 2*D
#define RR   4096          // L*BS
#define NB   64            // BS*NH batch count for attention

// Scratch (device globals: allocation-free kernel_launch)
__device__ float g_proj[(size_t)RR * PD];            // 32 MB (tf32-rounded)
__device__ float g_hid [(size_t)NHH * RR * LL];      // 268 MB (tf32-rounded)
__device__ float g_logits[(size_t)NB * LL * LL];     // 268 MB (raw logits + bias)
__device__ float g_outcat[(size_t)RR * DD];          // 17 MB (tf32-rounded)
__device__ float g_w1t[(size_t)NHH * LL * DHH];      // 4 MB  (rounded)
__device__ float g_w2t[(size_t)NHH * LL * LL];       // 64 MB (rounded)
__device__ float g_xr [(size_t)RR * DD];             // 16 MB (x rounded)
__device__ float g_wir[(size_t)PD * DD];             // 8 MB  (Wi rounded)
__device__ float g_wor[(size_t)DD * DD];             // 4 MB  (Wo rounded)
__device__ float g_vt [(size_t)BSZ * LL * LL];       // 16 MB (V^T per batch, rounded)

// ---------------------------------------------------------------------------
__device__ __forceinline__ uint32_t f2tf32(float f) {
    uint32_t u;
    asm("cvt.rna.tf32.f32 %0, %1;" : "=r"(u) : "f"(f));
    return u;
}
__device__ __forceinline__ float rndf(float f) { return __uint_as_float(f2tf32(f)); }

__device__ __forceinline__ uint32_t smem_u32(const void* p) {
    uint32_t a;
    asm("{ .reg .u64 t; cvta.to.shared.u64 t, %1; cvt.u32.u64 %0, t; }" : "=r"(a) : "l"(p));
    return a;
}
__device__ __forceinline__ void cp_async16(uint32_t dst, const void* src) {
    asm volatile("cp.async.cg.shared.global [%0], [%1], 16;" :: "r"(dst), "l"(src));
}
__device__ __forceinline__ void cp_commit() {
    asm volatile("cp.async.commit_group;" ::: "memory");
}
__device__ __forceinline__ void cp_wait1() {
    asm volatile("cp.async.wait_group 1;" ::: "memory");
}
__device__ __forceinline__ void ldsm4(uint32_t& r0, uint32_t& r1, uint32_t& r2, uint32_t& r3,
                                      uint32_t addr) {
    asm volatile("ldmatrix.sync.aligned.m8n8.x4.shared.b16 {%0,%1,%2,%3}, [%4];"
                 : "=r"(r0), "=r"(r1), "=r"(r2), "=r"(r3) : "r"(addr));
}
__device__ __forceinline__ void mma_tf32(float c[4], const uint32_t a[4], const uint32_t b[2]) {
    asm volatile(
        "mma.sync.aligned.m16n8k8.row.col.f32.tf32.tf32.f32 "
        "{%0,%1,%2,%3}, {%4,%5,%6,%7}, {%8,%9}, {%0,%1,%2,%3};"
        : "+f"(c[0]), "+f"(c[1]), "+f"(c[2]), "+f"(c[3])
        : "r"(a[0]), "r"(a[1]), "r"(a[2]), "r"(a[3]), "r"(b[0]), "r"(b[1]));
}

#define PADK 36
#define TS (16 * PADK * 4)                   // 16-row tile stride in bytes

// ---------------------------------------------------------------------------
// Generic 128x128-tile tf32 GEMM (modes 0=proj, 1=hid+relu, 3=out).
// 3-stage cp.async, ldmatrix, fragment double-buffer. 8 warps (4Mx2N).
// ---------------------------------------------------------------------------
#define STAGE_F (128 * PADK)
#define SMEM_BYTES (2 * 3 * STAGE_F * 4)     // 110592

__global__ void __launch_bounds__(256, 2) gemm_mma(
    int mode, int K, int relu,
    const float* __restrict__ Ain, const float* __restrict__ Bin,
    const float* __restrict__ biasIn, float* __restrict__ Cout)
{
    const int bm = blockIdx.y * 128;
    const int bn = blockIdx.x * 128;

    const float* A; const float* B; const float* bias; float* C;
    size_t sA, sB, ldc;
    if (mode == 0) {            // proj = x @ Wi^T + bi
        A = Ain; sA = DD; B = Bin; sB = DD; bias = biasIn; C = Cout; ldc = PD;
    } else if (mode == 1) {     // hid[h] = relu(proj[:, h*64:] @ w1t[h]^T + b1[h])
        int h = blockIdx.z;
        A = Ain + h * DHH;                sA = PD;
        B = Bin + (size_t)h * LL * DHH;   sB = DHH;
        bias = biasIn + h * LL;
        C = Cout + (size_t)h * RR * LL;   ldc = LL;
    } else {                    // out = outcat @ Wo^T + bo
        A = Ain; sA = DD; B = Bin; sB = DD; bias = biasIn; C = Cout; ldc = DD;
    }

    extern __shared__ __align__(16) float smem[];
    float* As = smem;                    // [3][128][PADK]
    float* Bs = smem + 3 * STAGE_F;      // [3][128][PADK]

    const int tid   = threadIdx.x;
    const int wid   = tid >> 5, lane = tid & 31;
    const int warpM = wid & 3;
    const int warpN = wid >> 2;
    const int grp   = lane >> 2;
    const int quad  = lane & 3;

    const int T = K / 32;

    const uint32_t sA0 = smem_u32(As);
    const uint32_t sB0 = smem_u32(Bs);
    const uint32_t aRow = (uint32_t)(((warpM * 32 + (lane & 15)) * PADK + (lane >> 4) * 4) * 4);
    const uint32_t bRow = (uint32_t)(((warpN * 64 + ((lane >> 4) & 1) * 8 + (lane & 7)) * PADK
                                      + ((lane >> 3) & 1) * 4) * 4);

    auto issue = [&](int chunk, int buf) {
        const int k0 = chunk * 32;
        float* sa = As + buf * STAGE_F;
        float* sb = Bs + buf * STAGE_F;
#pragma unroll
        for (int j = 0; j < 4; j++) {
            const int idx = tid + j * 256;
            const int r = idx >> 3, c4 = (idx & 7) * 4;
            cp_async16(smem_u32(&sa[r * PADK + c4]),
                       &A[(size_t)(bm + r) * sA + k0 + c4]);
            cp_async16(smem_u32(&sb[r * PADK + c4]),
                       &B[(size_t)(bn + r) * sB + k0 + c4]);
        }
    };

    issue(0, 0); cp_commit();
    if (1 < T) issue(1, 1);
    cp_commit();

    float acc[2][8][4] = {};
    uint32_t af[2][2][4], bf[2][8][2];

#pragma unroll 1
    for (int t = 0; t < T; t++) {
        cp_wait1();
        __syncthreads();

        if (t + 2 < T) issue(t + 2, (t + 2) % 3);
        cp_commit();

        const uint32_t aSt = sA0 + (uint32_t)((t % 3) * STAGE_F * 4);
        const uint32_t bSt = sB0 + (uint32_t)((t % 3) * STAGE_F * 4);

#pragma unroll
        for (int mt = 0; mt < 2; mt++)
            ldsm4(af[0][mt][0], af[0][mt][1], af[0][mt][2], af[0][mt][3],
                  aSt + aRow + mt * TS);
#pragma unroll
        for (int p = 0; p < 4; p++)
            ldsm4(bf[0][2*p][0], bf[0][2*p][1], bf[0][2*p+1][0], bf[0][2*p+1][1],
                  bSt + bRow + p * TS);

#pragma unroll
        for (int ks = 0; ks < 4; ks++) {
            const int cur = ks & 1, nxt = cur ^ 1;
            if (ks < 3) {
                const uint32_t ko = (uint32_t)((ks + 1) * 32);
#pragma unroll
                for (int mt = 0; mt < 2; mt++)
                    ldsm4(af[nxt][mt][0], af[nxt][mt][1], af[nxt][mt][2], af[nxt][mt][3],
                          aSt + aRow + mt * TS + ko);
#pragma unroll
                for (int p = 0; p < 4; p++)
                    ldsm4(bf[nxt][2*p][0], bf[nxt][2*p][1], bf[nxt][2*p+1][0], bf[nxt][2*p+1][1],
                          bSt + bRow + p * TS + ko);
            }
#pragma unroll
            for (int mt = 0; mt < 2; mt++)
#pragma unroll
                for (int nt = 0; nt < 8; nt++)
                    mma_tf32(acc[mt][nt], af[cur][mt], bf[cur][nt]);
        }
    }

    const bool rnd_out = (mode < 2);
#pragma unroll
    for (int mt = 0; mt < 2; mt++) {
        const int m = bm + warpM * 32 + mt * 16 + grp;
#pragma unroll
        for (int nt = 0; nt < 8; nt++) {
            const int n = bn + warpN * 64 + nt * 8 + quad * 2;
            float b0 = bias[n], b1 = bias[n + 1];
            float2 v0 = make_float2(acc[mt][nt][0] + b0, acc[mt][nt][1] + b1);
            float2 v1 = make_float2(acc[mt][nt][2] + b0, acc[mt][nt][3] + b1);
            if (relu) {
                v0.x = fmaxf(v0.x, 0.f); v0.y = fmaxf(v0.y, 0.f);
                v1.x = fmaxf(v1.x, 0.f); v1.y = fmaxf(v1.y, 0.f);
            }
            if (rnd_out) {
                v0.x = rndf(v0.x); v0.y = rndf(v0.y);
                v1.x = rndf(v1.x); v1.y = rndf(v1.y);
            }
            *(float2*)&C[(size_t)m * ldc + n]       = v0;
            *(float2*)&C[(size_t)(m + 8) * ldc + n] = v1;
        }
    }
}

// ---------------------------------------------------------------------------
// K3 logits kernel: 256x128 tile, 512 threads (16 warps, 4Mx4N, warp 64x32).
// Lower-tri tiles only (tj <= 2*ti2+1). 3-stage cp.async, single-buffer frags.
// logits[i][l][m] = hid[kq][l*4+bq][:] @ w2t[kq][m][:] + b2[kq][m]
// ---------------------------------------------------------------------------
#define BIG_AF (256 * PADK)
#define BIG_BF (128 * PADK)
#define BIG_SMEM (3 * (BIG_AF + BIG_BF) * 4)   // 165888

__global__ void __launch_bounds__(512, 1) gemm_logits_big(
    const float* __restrict__ w2t, const float* __restrict__ b2)
{
    const int ti2 = blockIdx.y, tj = blockIdx.x;
    if (tj > 2 * ti2 + 1) return;                 // causal: tri tiles only
    const int i  = blockIdx.z;
    const int kq = i >> 2, bq = i & 3;
    const float* A    = g_hid + (size_t)kq * RR * LL + bq * LL;   // stride 4*LL
    const float* B    = w2t + (size_t)kq * LL * LL;               // stride LL
    const float* bias = b2 + kq * LL;
    float* C          = g_logits + (size_t)i * LL * LL;

    const int bm = ti2 * 256;
    const int bn = tj * 128;

    extern __shared__ __align__(16) float smem[];
    float* As = smem;                      // [3][256][PADK]
    float* Bs = smem + 3 * BIG_AF;         // [3][128][PADK]

    const int tid   = threadIdx.x;
    const int wid   = tid >> 5, lane = tid & 31;
    const int warpM = wid & 3;             // 4 x 64 rows
    const int warpN = wid >> 2;            // 4 x 32 cols
    const int grp   = lane >> 2;
    const int quad  = lane & 3;

    const uint32_t sA0 = smem_u32(As);
    const uint32_t sB0 = smem_u32(Bs);
    const uint32_t aRow = (uint32_t)(((warpM * 64 + (lane & 15)) * PADK + (lane >> 4) * 4) * 4);
    const uint32_t bRow = (uint32_t)(((warpN * 32 + ((lane >> 4) & 1) * 8 + (lane & 7)) * PADK
                                      + ((lane >> 3) & 1) * 4) * 4);

    auto issue = [&](int chunk, int buf) {
        const int k0 = chunk * 32;
        float* sa = As + buf * BIG_AF;
        float* sb = Bs + buf * BIG_BF;
#pragma unroll
        for (int j = 0; j < 4; j++) {
            const int idx = tid + j * 512;           // 0..2047 -> 256 rows x 8 f4
            const int r = idx >> 3, c4 = (idx & 7) * 4;
            cp_async16(smem_u32(&sa[r * PADK + c4]),
                       &A[(size_t)(bm + r) * (4 * LL) + k0 + c4]);
        }
#pragma unroll
        for (int j = 0; j < 2; j++) {
            const int idx = tid + j * 512;           // 0..1023 -> 128 rows x 8 f4
            const int r = idx >> 3, c4 = (idx & 7) * 4;
            cp_async16(smem_u32(&sb[r * PADK + c4]),
                       &B[(size_t)(bn + r) * LL + k0 + c4]);
        }
    };

    const int T = LL / 32;                 // 32
    issue(0, 0); cp_commit();
    issue(1, 1); cp_commit();

    float acc[4][4][4] = {};
    uint32_t af[4][4], bf[4][2];

#pragma unroll 1
    for (int t = 0; t < T; t++) {
        cp_wait1();
        __syncthreads();

        if (t + 2 < T) issue(t + 2, (t + 2) % 3);
        cp_commit();

        const uint32_t aSt = sA0 + (uint32_t)((t % 3) * BIG_AF * 4);
        const uint32_t bSt = sB0 + (uint32_t)((t % 3) * BIG_BF * 4);

#pragma unroll
        for (int ks = 0; ks < 4; ks++) {
            const uint32_t ko = (uint32_t)(ks * 32);
#pragma unroll
            for (int mt = 0; mt < 4; mt++)
                ldsm4(af[mt][0], af[mt][1], af[mt][2], af[mt][3],
                      aSt + aRow + mt * TS + ko);
#pragma unroll
            for (int p = 0; p < 2; p++)
                ldsm4(bf[2*p][0], bf[2*p][1], bf[2*p+1][0], bf[2*p+1][1],
                      bSt + bRow + p * TS + ko);
#pragma unroll
            for (int mt = 0; mt < 4; mt++)
#pragma unroll
                for (int nt = 0; nt < 4; nt++)
                    mma_tf32(acc[mt][nt], af[mt], bf[nt]);
        }
    }

#pragma unroll
    for (int mt = 0; mt < 4; mt++) {
        const int m = bm + warpM * 64 + mt * 16 + grp;
#pragma unroll
        for (int nt = 0; nt < 4; nt++) {
            const int n = bn + warpN * 32 + nt * 8 + quad * 2;
            float b0 = bias[n], b1 = bias[n + 1];
            float2 v0 = make_float2(acc[mt][nt][0] + b0, acc[mt][nt][1] + b1);
            float2 v1 = make_float2(acc[mt][nt][2] + b0, acc[mt][nt][3] + b1);
            *(float2*)&C[(size_t)m * LL + n]       = v0;
            *(float2*)&C[(size_t)(m + 8) * LL + n] = v1;
        }
    }
}

// ---------------------------------------------------------------------------
// Fused softmax + PV: per CTA = (row tile ti, batch i).
// Pass A: online max/sum over each row (single read of valid cols).
// Pass B: stage rounded probs via LDG+exp+STS, tf32 mma vs cp.async'd V^T.
// Writes concat layout (tf32-rounded, feeds K6).
// ---------------------------------------------------------------------------
__global__ void __launch_bounds__(256, 2) pv_fused()
{
    const int i  = blockIdx.y;
    const int ti = 7 - blockIdx.x;                 // big tiles first
    const int bv = i >> 4, kv = i & 15;
    const float* P  = g_logits + (size_t)i * LL * LL;
    const float* Vt = g_vt + (size_t)bv * LL * LL + (size_t)(kv * DHH) * LL;

    __shared__ __align__(16) float Aps[128 * PADK];
    __shared__ __align__(16) float Bps[2][64 * PADK];
    __shared__ float rm[256], rs[256];
    __shared__ float sm_m[128], sm_inv[128];

    const int tid = threadIdx.x;
    const int wid = tid >> 5, lane = tid & 31;
    const int grp = lane >> 2, quad = lane & 3;
    const int bm  = ti * 128;
    const int T   = (ti + 1) * 4;                  // K chunks of 32

    // ---- pass A: online row max/sum (2 threads per row, strided float4) ----
    {
        const int r = tid & 127, h = tid >> 7;
        const float* row = P + (size_t)(bm + r) * LL;
        const int n = bm + r + 1;
        const int nf4 = (n + 3) >> 2;
        float m = -1e30f, s = 0.f;
        for (int f = h; f < nf4; f += 2) {
            float4 v = *(const float4*)&row[f * 4];
            const int c = f * 4;
            float vm = -1e30f;
            if (c + 0 < n) vm = v.x;
            if (c + 1 < n) vm = fmaxf(vm, v.y);
            if (c + 2 < n) vm = fmaxf(vm, v.z);
            if (c + 3 < n) vm = fmaxf(vm, v.w);
            if (vm > m) { s *= __expf(m - vm); m = vm; }
            if (c + 0 < n) s += __expf(v.x - m);
            if (c + 1 < n) s += __expf(v.y - m);
            if (c + 2 < n) s += __expf(v.z - m);
            if (c + 3 < n) s += __expf(v.w - m);
        }
        rm[tid] = m; rs[tid] = s;
        __syncthreads();
        if (h == 0) {
            float m1 = rm[tid + 128], s1 = rs[tid + 128];
            float mm = fmaxf(m, m1);
            float ss = s * __expf(m - mm) + s1 * __expf(m1 - mm);
            sm_m[r] = mm;
            sm_inv[r] = 1.0f / ss;
        }
        __syncthreads();
    }

    // ---- pass B: staged-prob mma ----
    const uint32_t aSt = smem_u32(Aps);
    const uint32_t bS0 = smem_u32(Bps);
    const uint32_t aRow = (uint32_t)(((wid * 16 + (lane & 15)) * PADK + (lane >> 4) * 4) * 4);
    const uint32_t bRow = (uint32_t)(((((lane >> 4) & 1) * 8 + (lane & 7)) * PADK
                                      + ((lane >> 3) & 1) * 4) * 4);

    auto issueB = [&](int chunk) {
        const int k0 = chunk * 32;
        float* sb = (float*)Bps[chunk & 1];
#pragma unroll
        for (int j = 0; j < 2; j++) {
            const int idx = tid + j * 256;
            const int r = idx >> 3, c4 = (idx & 7) * 4;
            cp_async16(smem_u32(&sb[r * PADK + c4]),
                       &Vt[(size_t)r * LL + k0 + c4]);
        }
    };

    issueB(0); cp_commit();

    float acc[8][4] = {};
    uint32_t af[4], bf[8][2];

#pragma unroll 1
    for (int t = 0; t < T; t++) {
        if (t + 1 < T) issueB(t + 1);
        cp_commit();

        // stage A = rounded probs for chunk t
        const int k0 = t * 32;
#pragma unroll
        for (int j = 0; j < 4; j++) {
            const int idx = tid + j * 256;
            const int r = idx >> 3, c4 = (idx & 7) * 4;
            float4 v = *(const float4*)&P[(size_t)(bm + r) * LL + k0 + c4];
            const int n = bm + r + 1;
            const float mr = sm_m[r], ir = sm_inv[r];
            const int c = k0 + c4;
            float4 o;
            o.x = (c + 0 < n) ? rndf(__expf(v.x - mr) * ir) : 0.f;
            o.y = (c + 1 < n) ? rndf(__expf(v.y - mr) * ir) : 0.f;
            o.z = (c + 2 < n) ? rndf(__expf(v.z - mr) * ir) : 0.f;
            o.w = (c + 3 < n) ? rndf(__expf(v.w - mr) * ir) : 0.f;
            *(float4*)&Aps[r * PADK + c4] = o;
        }
        cp_wait1();
        __syncthreads();

        const uint32_t bSt = bS0 + (uint32_t)((t & 1) * 64 * PADK * 4);
#pragma unroll
        for (int ks = 0; ks < 4; ks++) {
            const uint32_t ko = (uint32_t)(ks * 32);
            ldsm4(af[0], af[1], af[2], af[3], aSt + aRow + ko);
#pragma unroll
            for (int p = 0; p < 4; p++)
                ldsm4(bf[2*p][0], bf[2*p][1], bf[2*p+1][0], bf[2*p+1][1],
                      bSt + bRow + p * TS + ko);
#pragma unroll
            for (int nt = 0; nt < 8; nt++)
                mma_tf32(acc[nt], af, bf[nt]);
        }
        __syncthreads();
    }

    const int l0 = bm + wid * 16 + grp;
#pragma unroll
    for (int nt = 0; nt < 8; nt++) {
        const int d = nt * 8 + quad * 2;
        float* dst0 = g_outcat + ((size_t)l0 * 4 + bv) * DD + kv * DHH + d;
        float* dst1 = g_outcat + ((size_t)(l0 + 8) * 4 + bv) * DD + kv * DHH + d;
        dst0[0] = rndf(acc[nt][0]); dst0[1] = rndf(acc[nt][1]);
        dst1[0] = rndf(acc[nt][2]); dst1[1] = rndf(acc[nt][3]);
    }
}

// ---------------------------------------------------------------------------
// Prep kernels
// ---------------------------------------------------------------------------
__global__ void round_copy(const float* __restrict__ src, float* __restrict__ dst, int n4)
{
    int i = blockIdx.x * blockDim.x + threadIdx.x;
    if (i < n4) {
        float4 v = ((const float4*)src)[i];
        v.x = rndf(v.x); v.y = rndf(v.y); v.z = rndf(v.z); v.w = rndf(v.w);
        ((float4*)dst)[i] = v;
    }
}

__global__ void transpose_rk(const float* __restrict__ src, float* __restrict__ dst,
                             int R, int C)
{
    __shared__ float t[32][33];
    const size_t zo = (size_t)blockIdx.z * R * C;
    const int c0 = blockIdx.x * 32, r0 = blockIdx.y * 32;
    const int tx = threadIdx.x, ty = threadIdx.y;
#pragma unroll
    for (int j = 0; j < 32; j += 8)
        t[ty + j][tx] = rndf(src[zo + (size_t)(r0 + ty + j) * C + c0 + tx]);
    __syncthreads();
#pragma unroll
    for (int j = 0; j < 32; j += 8)
        dst[zo + (size_t)(c0 + ty + j) * R + r0 + tx] = t[tx][ty + j];
}

// g_vt[bv][dcol][m] = proj[(m*4+bv)*PD + DD + dcol]  (already rounded)
__global__ void transpose_v()
{
    __shared__ float t[32][33];
    const int bv = blockIdx.z;
    const int c0 = blockIdx.x * 32, r0 = blockIdx.y * 32;
    const int tx = threadIdx.x, ty = threadIdx.y;
#pragma unroll
    for (int j = 0; j < 32; j += 8)
        t[ty + j][tx] = g_proj[((size_t)(r0 + ty + j) * 4 + bv) * PD + DD + c0 + tx];
    __syncthreads();
#pragma unroll
    for (int j = 0; j < 32; j += 8)
        g_vt[(size_t)bv * LL * LL + (size_t)(c0 + ty + j) * LL + r0 + tx] = t[tx][ty + j];
}

// ---------------------------------------------------------------------------
extern "C" void kernel_launch(void* const* d_in, const int* in_sizes, int n_in,
                              void* d_out, int out_size)
{
    (void)in_sizes; (void)n_in; (void)out_size;
    const float* x  = (const float*)d_in[0];
    // d_in[1] = attention_mask (exactly causal; implemented structurally)
    const float* Wi = (const float*)d_in[2];
    const float* bi = (const float*)d_in[3];
    const float* w1 = (const float*)d_in[4];
    const float* b1 = (const float*)d_in[5];
    const float* w2 = (const float*)d_in[6];
    const float* b2 = (const float*)d_in[7];
    const float* Wo = (const float*)d_in[8];
    const float* bo = (const float*)d_in[9];
    float* out = (float*)d_out;

    float *proj, *hid, *w1t, *w2t, *xr, *wir, *wor, *outcat;
    cudaGetSymbolAddress((void**)&proj,   g_proj);
    cudaGetSymbolAddress((void**)&hid,    g_hid);
    cudaGetSymbolAddress((void**)&w1t,    g_w1t);
    cudaGetSymbolAddress((void**)&w2t,    g_w2t);
    cudaGetSymbolAddress((void**)&xr,     g_xr);
    cudaGetSymbolAddress((void**)&wir,    g_wir);
    cudaGetSymbolAddress((void**)&wor,    g_wor);
    cudaGetSymbolAddress((void**)&outcat, g_outcat);

    cudaFuncSetAttribute(gemm_mma,        cudaFuncAttributeMaxDynamicSharedMemorySize, SMEM_BYTES);
    cudaFuncSetAttribute(gemm_logits_big, cudaFuncAttributeMaxDynamicSharedMemorySize, BIG_SMEM);

    // prep: round external mma inputs; transpose w1/w2 (rounded)
    round_copy<<<(RR*DD/4 + 255)/256, 256>>>(x,  xr,  RR*DD/4);
    round_copy<<<(PD*DD/4 + 255)/256, 256>>>(Wi, wir, PD*DD/4);
    round_copy<<<(DD*DD/4 + 255)/256, 256>>>(Wo, wor, DD*DD/4);
    transpose_rk<<<dim3(32, 2, NHH),  dim3(32, 8)>>>(w1, w1t, DHH, LL);
    transpose_rk<<<dim3(32, 32, NHH), dim3(32, 8)>>>(w2, w2t, LL, LL);

    // K1: proj = x @ Wi^T + bi                 (4096 x 2048 x 1024)
    gemm_mma<<<dim3(PD/128, RR/128), 256, SMEM_BYTES>>>(0, DD, 0, xr, wir, bi, proj);
    // V^T per batch (from rounded proj)
    transpose_v<<<dim3(32, 32, BSZ), dim3(32, 8)>>>();
    // K2: hid = relu(q @ w1 + b1)              (16 x [4096 x 1024 x 64])
    gemm_mma<<<dim3(LL/128, RR/128, NHH), 256, SMEM_BYTES>>>(1, DHH, 1, proj, w1t, b1, hid);
    // K3: logits (256x128 tri tiles) + b2      (64 x tri[1024 x 1024 x 1024])
    gemm_logits_big<<<dim3(LL/128, LL/256, NB), 512, BIG_SMEM>>>(w2t, b2);
    // K4+K5 fused: softmax + PV -> concat layout
    pv_fused<<<dim3(LL/128, NB), 256>>>();
    // K6: y = outcat @ Wo^T + bo               (4096 x 1024 x 1024)
    gemm_mma<<<dim3(DD/128, RR/128), 256, SMEM_BYTES>>>(3, DD, 0, outcat, wor, bo, out);
}

// round 7
// speedup vs baseline: 1.2020x; 1.2020x over previous
#include <cuda_runtime.h>
#include <cstdint>
#include <math.h>

// Shapes (fixed by the problem)
#define LL   1024
#define BSZ  4
#define DD   1024
#define NHH  16
#define DHH  64
#define PD   2048          // 2*D
#define RR   4096          // L*BS
#define NB   64            // BS*NH batch count for attention

// Scratch (device globals: allocation-free kernel_launch)
__device__ float g_proj[(size_t)RR * PD];            // 32 MB (tf32-rounded)
__device__ float g_hid [(size_t)NHH * RR * LL];      // 268 MB (tf32-rounded)
__device__ float g_logits[(size_t)NB * LL * LL];     // 268 MB
__device__ float g_outcat[(size_t)RR * DD];          // 17 MB (tf32-rounded)
__device__ float g_w1t[(size_t)NHH * LL * DHH];      // 4 MB  (rounded)
__device__ float g_w2t[(size_t)NHH * LL * LL];       // 64 MB (rounded)
__device__ float g_xr [(size_t)RR * DD];             // 16 MB (x rounded)
__device__ float g_wir[(size_t)PD * DD];             // 8 MB  (Wi rounded)
__device__ float g_wor[(size_t)DD * DD];             // 4 MB  (Wo rounded)
__device__ float g_vt [(size_t)BSZ * LL * LL];       // 16 MB (V^T per batch, rounded)

// ---------------------------------------------------------------------------
__device__ __forceinline__ uint32_t f2tf32(float f) {
    uint32_t u;
    asm("cvt.rna.tf32.f32 %0, %1;" : "=r"(u) : "f"(f));
    return u;
}
__device__ __forceinline__ float rndf(float f) { return __uint_as_float(f2tf32(f)); }

__device__ __forceinline__ uint32_t smem_u32(const void* p) {
    uint32_t a;
    asm("{ .reg .u64 t; cvta.to.shared.u64 t, %1; cvt.u32.u64 %0, t; }" : "=r"(a) : "l"(p));
    return a;
}
__device__ __forceinline__ void cp_async16(uint32_t dst, const void* src) {
    asm volatile("cp.async.cg.shared.global [%0], [%1], 16;" :: "r"(dst), "l"(src));
}
__device__ __forceinline__ void cp_commit() {
    asm volatile("cp.async.commit_group;" ::: "memory");
}
__device__ __forceinline__ void cp_wait1() {
    asm volatile("cp.async.wait_group 1;" ::: "memory");
}
__device__ __forceinline__ void ldsm4(uint32_t& r0, uint32_t& r1, uint32_t& r2, uint32_t& r3,
                                      uint32_t addr) {
    asm volatile("ldmatrix.sync.aligned.m8n8.x4.shared.b16 {%0,%1,%2,%3}, [%4];"
                 : "=r"(r0), "=r"(r1), "=r"(r2), "=r"(r3) : "r"(addr));
}
__device__ __forceinline__ void mma_tf32(float c[4], const uint32_t a[4], const uint32_t b[2]) {
    asm volatile(
        "mma.sync.aligned.m16n8k8.row.col.f32.tf32.tf32.f32 "
        "{%0,%1,%2,%3}, {%4,%5,%6,%7}, {%8,%9}, {%0,%1,%2,%3};"
        : "+f"(c[0]), "+f"(c[1]), "+f"(c[2]), "+f"(c[3])
        : "r"(a[0]), "r"(a[1]), "r"(a[2]), "r"(a[3]), "r"(b[0]), "r"(b[1]));
}

#define PADK 36
#define TS (16 * PADK * 4)                   // 16-row tile stride in bytes

// ---------------------------------------------------------------------------
// Tensor-core tf32 GEMM: C = act(A @ B^T + bias). Inputs pre-rounded to tf32.
// Block tile 128x128, K-chunk 32, 3-stage cp.async, ldmatrix fragment loads,
// fragment double-buffering. 8 warps (4M x 2N), warp tile 32x64.
// mode: 0=proj  1=hid(relu)  2=logits(tri-packed grid)  3=out
// ---------------------------------------------------------------------------
#define STAGE_F (128 * PADK)
#define SMEM_BYTES (2 * 3 * STAGE_F * 4)     // 110592

__global__ void __launch_bounds__(256, 2) gemm_mma(
    int mode, int K, int relu,
    const float* __restrict__ Ain, const float* __restrict__ Bin,
    const float* __restrict__ biasIn, float* __restrict__ Cout)
{
    int bm, bn;
    const float* A; const float* B; const float* bias; float* C;
    size_t sA, sB, ldc;
    if (mode == 0) {            // proj = x @ Wi^T + bi
        bm = blockIdx.y * 128; bn = blockIdx.x * 128;
        A = Ain; sA = DD; B = Bin; sB = DD; bias = biasIn; C = Cout; ldc = PD;
    } else if (mode == 1) {     // hid[h] = relu(proj[:, h*64:] @ w1t[h]^T + b1[h])
        bm = blockIdx.y * 128; bn = blockIdx.x * 128;
        int h = blockIdx.z;
        A = Ain + h * DHH;                sA = PD;
        B = Bin + (size_t)h * LL * DHH;   sB = DHH;
        bias = biasIn + h * LL;
        C = Cout + (size_t)h * RR * LL;   ldc = LL;
    } else if (mode == 2) {     // logits: tri-packed 36 tiles per batch
        const int t = blockIdx.x;                 // 0..35
        int ti = (int)((sqrtf(8.0f * t + 1.0f) - 1.0f) * 0.5f);
        if (t < ti * (ti + 1) / 2) ti--;
        const int tj = t - ti * (ti + 1) / 2;
        bm = ti * 128; bn = tj * 128;
        int i = blockIdx.z, kq = i >> 2, bq = i & 3;
        A = Ain + (size_t)kq * RR * LL + bq * LL; sA = 4 * LL;
        B = Bin + (size_t)kq * LL * LL;           sB = LL;
        bias = biasIn + kq * LL;
        C = Cout + (size_t)i * LL * LL;           ldc = LL;
    } else {                    // out = outcat @ Wo^T + bo
        bm = blockIdx.y * 128; bn = blockIdx.x * 128;
        A = Ain; sA = DD; B = Bin; sB = DD; bias = biasIn; C = Cout; ldc = DD;
    }

    extern __shared__ __align__(16) float smem[];
    float* As = smem;                    // [3][128][PADK]
    float* Bs = smem + 3 * STAGE_F;      // [3][128][PADK]

    const int tid   = threadIdx.x;
    const int wid   = tid >> 5, lane = tid & 31;
    const int warpM = wid & 3;
    const int warpN = wid >> 2;
    const int grp   = lane >> 2;
    const int quad  = lane & 3;

    const int T = K / 32;

    const uint32_t sA0 = smem_u32(As);
    const uint32_t sB0 = smem_u32(Bs);
    const uint32_t aRow = (uint32_t)(((warpM * 32 + (lane & 15)) * PADK + (lane >> 4) * 4) * 4);
    const uint32_t bRow = (uint32_t)(((warpN * 64 + ((lane >> 4) & 1) * 8 + (lane & 7)) * PADK
                                      + ((lane >> 3) & 1) * 4) * 4);

    auto issue = [&](int chunk, int buf) {
        const int k0 = chunk * 32;
        float* sa = As + buf * STAGE_F;
        float* sb = Bs + buf * STAGE_F;
#pragma unroll
        for (int j = 0; j < 4; j++) {
            const int idx = tid + j * 256;
            const int r = idx >> 3, c4 = (idx & 7) * 4;
            cp_async16(smem_u32(&sa[r * PADK + c4]),
                       &A[(size_t)(bm + r) * sA + k0 + c4]);
            cp_async16(smem_u32(&sb[r * PADK + c4]),
                       &B[(size_t)(bn + r) * sB + k0 + c4]);
        }
    };

    issue(0, 0); cp_commit();
    if (1 < T) issue(1, 1);
    cp_commit();

    float acc[2][8][4] = {};
    uint32_t af[2][2][4], bf[2][8][2];

#pragma unroll 1
    for (int t = 0; t < T; t++) {
        cp_wait1();
        __syncthreads();

        if (t + 2 < T) issue(t + 2, (t + 2) % 3);
        cp_commit();

        const uint32_t aSt = sA0 + (uint32_t)((t % 3) * STAGE_F * 4);
        const uint32_t bSt = sB0 + (uint32_t)((t % 3) * STAGE_F * 4);

#pragma unroll
        for (int mt = 0; mt < 2; mt++)
            ldsm4(af[0][mt][0], af[0][mt][1], af[0][mt][2], af[0][mt][3],
                  aSt + aRow + mt * TS);
#pragma unroll
        for (int p = 0; p < 4; p++)
            ldsm4(bf[0][2*p][0], bf[0][2*p][1], bf[0][2*p+1][0], bf[0][2*p+1][1],
                  bSt + bRow + p * TS);

#pragma unroll
        for (int ks = 0; ks < 4; ks++) {
            const int cur = ks & 1, nxt = cur ^ 1;
            if (ks < 3) {
                const uint32_t ko = (uint32_t)((ks + 1) * 32);
#pragma unroll
                for (int mt = 0; mt < 2; mt++)
                    ldsm4(af[nxt][mt][0], af[nxt][mt][1], af[nxt][mt][2], af[nxt][mt][3],
                          aSt + aRow + mt * TS + ko);
#pragma unroll
                for (int p = 0; p < 4; p++)
                    ldsm4(bf[nxt][2*p][0], bf[nxt][2*p][1], bf[nxt][2*p+1][0], bf[nxt][2*p+1][1],
                          bSt + bRow + p * TS + ko);
            }
#pragma unroll
            for (int mt = 0; mt < 2; mt++)
#pragma unroll
                for (int nt = 0; nt < 8; nt++)
                    mma_tf32(acc[mt][nt], af[cur][mt], bf[cur][nt]);
        }
    }

    const bool rnd_out = (mode < 2);
#pragma unroll
    for (int mt = 0; mt < 2; mt++) {
        const int m = bm + warpM * 32 + mt * 16 + grp;
#pragma unroll
        for (int nt = 0; nt < 8; nt++) {
            const int n = bn + warpN * 64 + nt * 8 + quad * 2;
            float b0 = bias[n], b1 = bias[n + 1];
            float2 v0 = make_float2(acc[mt][nt][0] + b0, acc[mt][nt][1] + b1);
            float2 v1 = make_float2(acc[mt][nt][2] + b0, acc[mt][nt][3] + b1);
            if (relu) {
                v0.x = fmaxf(v0.x, 0.f); v0.y = fmaxf(v0.y, 0.f);
                v1.x = fmaxf(v1.x, 0.f); v1.y = fmaxf(v1.y, 0.f);
            }
            if (rnd_out) {
                v0.x = rndf(v0.x); v0.y = rndf(v0.y);
                v1.x = rndf(v1.x); v1.y = rndf(v1.y);
            }
            *(float2*)&C[(size_t)m * ldc + n]       = v0;
            *(float2*)&C[(size_t)(m + 8) * ldc + n] = v1;
        }
    }
}

// ---------------------------------------------------------------------------
// PV with tf32 mma: out[i] = probs[i] @ V[i], V pre-transposed K-major in g_vt.
// Block tile 128x64, K-chunk 32, 3-stage cp.async, ldmatrix. 8 warps 16x64.
// ---------------------------------------------------------------------------
#define PV_AF (128 * PADK)
#define PV_BF (64 * PADK)
#define PV_SMEM (3 * (PV_AF + PV_BF) * 4)    // 82944

__global__ void __launch_bounds__(256, 2) gemm_pv_mma()
{
    const int i  = blockIdx.y;
    const int ti = blockIdx.x;
    const int bv = i >> 4, kv = i & 15;
    const float* P  = g_logits + (size_t)i * LL * LL;
    const float* Vt = g_vt + (size_t)bv * LL * LL + (size_t)(kv * DHH) * LL;

    extern __shared__ __align__(16) float smem[];
    float* As = smem;                         // [3][128][PADK]
    float* Bs = smem + 3 * PV_AF;             // [3][64][PADK]

    const int tid = threadIdx.x;
    const int wid = tid >> 5, lane = tid & 31;
    const int grp = lane >> 2, quad = lane & 3;
    const int bm  = ti * 128;
    const int T   = (ti + 1) * 4;

    const uint32_t sA0 = smem_u32(As);
    const uint32_t sB0 = smem_u32(Bs);
    const uint32_t aRow = (uint32_t)(((wid * 16 + (lane & 15)) * PADK + (lane >> 4) * 4) * 4);
    const uint32_t bRow = (uint32_t)(((((lane >> 4) & 1) * 8 + (lane & 7)) * PADK
                                      + ((lane >> 3) & 1) * 4) * 4);

    auto issue = [&](int chunk, int buf) {
        const int k0 = chunk * 32;
        float* sa = As + buf * PV_AF;
        float* sb = Bs + buf * PV_BF;
#pragma unroll
        for (int j = 0; j < 4; j++) {
            const int idx = tid + j * 256;
            const int r = idx >> 3, c4 = (idx & 7) * 4;
            cp_async16(smem_u32(&sa[r * PADK + c4]),
                       &P[(size_t)(bm + r) * LL + k0 + c4]);
        }
#pragma unroll
        for (int j = 0; j < 2; j++) {
            const int idx = tid + j * 256;
            const int r = idx >> 3, c4 = (idx & 7) * 4;
            cp_async16(smem_u32(&sb[r * PADK + c4]),
                       &Vt[(size_t)r * LL + k0 + c4]);
        }
    };

    issue(0, 0); cp_commit();
    issue(1, 1); cp_commit();

    float acc[8][4] = {};
    uint32_t af[2][4], bf[2][8][2];

#pragma unroll 1
    for (int t = 0; t < T; t++) {
        cp_wait1();
        __syncthreads();

        if (t + 2 < T) issue(t + 2, (t + 2) % 3);
        cp_commit();

        const uint32_t aSt = sA0 + (uint32_t)((t % 3) * PV_AF * 4);
        const uint32_t bSt = sB0 + (uint32_t)((t % 3) * PV_BF * 4);

        ldsm4(af[0][0], af[0][1], af[0][2], af[0][3], aSt + aRow);
#pragma unroll
        for (int p = 0; p < 4; p++)
            ldsm4(bf[0][2*p][0], bf[0][2*p][1], bf[0][2*p+1][0], bf[0][2*p+1][1],
                  bSt + bRow + p * TS);

#pragma unroll
        for (int ks = 0; ks < 4; ks++) {
            const int cur = ks & 1, nxt = cur ^ 1;
            if (ks < 3) {
                const uint32_t ko = (uint32_t)((ks + 1) * 32);
                ldsm4(af[nxt][0], af[nxt][1], af[nxt][2], af[nxt][3], aSt + aRow + ko);
#pragma unroll
                for (int p = 0; p < 4; p++)
                    ldsm4(bf[nxt][2*p][0], bf[nxt][2*p][1], bf[nxt][2*p+1][0], bf[nxt][2*p+1][1],
                          bSt + bRow + p * TS + ko);
            }
#pragma unroll
            for (int nt = 0; nt < 8; nt++)
                mma_tf32(acc[nt], af[cur], bf[cur][nt]);
        }
    }

    const int l0 = bm + wid * 16 + grp;
#pragma unroll
    for (int nt = 0; nt < 8; nt++) {
        const int d = nt * 8 + quad * 2;
        float* dst0 = g_outcat + ((size_t)l0 * 4 + bv) * DD + kv * DHH + d;
        float* dst1 = g_outcat + ((size_t)(l0 + 8) * 4 + bv) * DD + kv * DHH + d;
        dst0[0] = rndf(acc[nt][0]); dst0[1] = rndf(acc[nt][1]);
        dst1[0] = rndf(acc[nt][2]); dst1[1] = rndf(acc[nt][3]);
    }
}

// ---------------------------------------------------------------------------
// Prep: single launch rounding x, Wi, Wo into g_xr, g_wir, g_wor.
// ---------------------------------------------------------------------------
#define N4_X  (RR * DD / 4)
#define N4_WI (PD * DD / 4)
#define N4_WO (DD * DD / 4)
#define N4_ALL (N4_X + N4_WI + N4_WO)

__global__ void round_all(const float* __restrict__ x, const float* __restrict__ Wi,
                          const float* __restrict__ Wo)
{
    int i = blockIdx.x * blockDim.x + threadIdx.x;
    if (i >= N4_ALL) return;
    const float4* src; float4* dst; int j = i;
    if (j < N4_X)            { src = (const float4*)x;  dst = (float4*)g_xr;  }
    else if ((j -= N4_X) < N4_WI) { src = (const float4*)Wi; dst = (float4*)g_wir; }
    else { j -= N4_WI;         src = (const float4*)Wo; dst = (float4*)g_wor; }
    float4 v = src[j];
    v.x = rndf(v.x); v.y = rndf(v.y); v.z = rndf(v.z); v.w = rndf(v.w);
    dst[j] = v;
}

__global__ void transpose_rk(const float* __restrict__ src, float* __restrict__ dst,
                             int R, int C)
{
    __shared__ float t[32][33];
    const size_t zo = (size_t)blockIdx.z * R * C;
    const int c0 = blockIdx.x * 32, r0 = blockIdx.y * 32;
    const int tx = threadIdx.x, ty = threadIdx.y;
#pragma unroll
    for (int j = 0; j < 32; j += 8)
        t[ty + j][tx] = rndf(src[zo + (size_t)(r0 + ty + j) * C + c0 + tx]);
    __syncthreads();
#pragma unroll
    for (int j = 0; j < 32; j += 8)
        dst[zo + (size_t)(c0 + ty + j) * R + r0 + tx] = t[tx][ty + j];
}

// g_vt[bv][dcol][m] = proj[(m*4+bv)*PD + DD + dcol]  (already rounded)
__global__ void transpose_v()
{
    __shared__ float t[32][33];
    const int bv = blockIdx.z;
    const int c0 = blockIdx.x * 32, r0 = blockIdx.y * 32;
    const int tx = threadIdx.x, ty = threadIdx.y;
#pragma unroll
    for (int j = 0; j < 32; j += 8)
        t[ty + j][tx] = g_proj[((size_t)(r0 + ty + j) * 4 + bv) * PD + DD + c0 + tx];
    __syncthreads();
#pragma unroll
    for (int j = 0; j < 32; j += 8)
        g_vt[(size_t)bv * LL * LL + (size_t)(c0 + ty + j) * LL + r0 + tx] = t[tx][ty + j];
}

// ---------------------------------------------------------------------------
// Register causal softmax; writes tf32-rounded probs. Masked cols -> 0.
// ---------------------------------------------------------------------------
__global__ void __launch_bounds__(256) softmax_causal()
{
    const int l = blockIdx.x;
    const int i = blockIdx.y;
    float* row = g_logits + ((size_t)i * LL + l) * LL;
    const int n = l + 1;
    const int diagEnd = ((l >> 7) + 1) << 7;

    const int t = threadIdx.x;
    const int c = t * 4;
    const bool inRange = (c < diagEnd);

    __shared__ float red[8];
    const int wid = t >> 5, lane = t & 31;

    float4 v = make_float4(0.f, 0.f, 0.f, 0.f);
    if (inRange) v = *(const float4*)&row[c];

    bool m0 = (c + 0) < n, m1 = (c + 1) < n, m2 = (c + 2) < n, m3 = (c + 3) < n;

    float vmax = -1e30f;
    if (m0) vmax = v.x;
    if (m1) vmax = fmaxf(vmax, v.y);
    if (m2) vmax = fmaxf(vmax, v.z);
    if (m3) vmax = fmaxf(vmax, v.w);
#pragma unroll
    for (int o = 16; o; o >>= 1) vmax = fmaxf(vmax, __shfl_xor_sync(0xFFFFFFFF, vmax, o));
    if (lane == 0) red[wid] = vmax;
    __syncthreads();
    vmax = red[0];
#pragma unroll
    for (int j = 1; j < 8; j++) vmax = fmaxf(vmax, red[j]);
    __syncthreads();

    float e0 = m0 ? __expf(v.x - vmax) : 0.f;
    float e1 = m1 ? __expf(v.y - vmax) : 0.f;
    float e2 = m2 ? __expf(v.z - vmax) : 0.f;
    float e3 = m3 ? __expf(v.w - vmax) : 0.f;
    float s = e0 + e1 + e2 + e3;
#pragma unroll
    for (int o = 16; o; o >>= 1) s += __shfl_xor_sync(0xFFFFFFFF, s, o);
    if (lane == 0) red[wid] = s;
    __syncthreads();
    s = red[0];
#pragma unroll
    for (int j = 1; j < 8; j++) s += red[j];
    const float inv = 1.0f / s;

    if (inRange) {
        float4 o = make_float4(rndf(e0 * inv), rndf(e1 * inv), rndf(e2 * inv), rndf(e3 * inv));
        *(float4*)&row[c] = o;
    }
}

// ---------------------------------------------------------------------------
extern "C" void kernel_launch(void* const* d_in, const int* in_sizes, int n_in,
                              void* d_out, int out_size)
{
    (void)in_sizes; (void)n_in; (void)out_size;
    const float* x  = (const float*)d_in[0];
    // d_in[1] = attention_mask (exactly causal; implemented structurally)
    const float* Wi = (const float*)d_in[2];
    const float* bi = (const float*)d_in[3];
    const float* w1 = (const float*)d_in[4];
    const float* b1 = (const float*)d_in[5];
    const float* w2 = (const float*)d_in[6];
    const float* b2 = (const float*)d_in[7];
    const float* Wo = (const float*)d_in[8];
    const float* bo = (const float*)d_in[9];
    float* out = (float*)d_out;

    float *proj, *hid, *logits, *w1t, *w2t, *xr, *wir, *wor, *outcat;
    cudaGetSymbolAddress((void**)&proj,   g_proj);
    cudaGetSymbolAddress((void**)&hid,    g_hid);
    cudaGetSymbolAddress((void**)&logits, g_logits);
    cudaGetSymbolAddress((void**)&w1t,    g_w1t);
    cudaGetSymbolAddress((void**)&w2t,    g_w2t);
    cudaGetSymbolAddress((void**)&xr,     g_xr);
    cudaGetSymbolAddress((void**)&wir,    g_wir);
    cudaGetSymbolAddress((void**)&wor,    g_wor);
    cudaGetSymbolAddress((void**)&outcat, g_outcat);

    cudaFuncSetAttribute(gemm_mma,    cudaFuncAttributeMaxDynamicSharedMemorySize, SMEM_BYTES);
    cudaFuncSetAttribute(gemm_pv_mma, cudaFuncAttributeMaxDynamicSharedMemorySize, PV_SMEM);

    // 1: round x/Wi/Wo in one launch
    round_all<<<(N4_ALL + 255) / 256, 256>>>(x, Wi, Wo);
    // 2,3: weight transposes to K-major (rounded)
    transpose_rk<<<dim3(32, 2, NHH),  dim3(32, 8)>>>(w1, w1t, DHH, LL);
    transpose_rk<<<dim3(32, 32, NHH), dim3(32, 8)>>>(w2, w2t, LL, LL);
    // 4: K1 proj = x @ Wi^T + bi               (4096 x 2048 x 1024)
    gemm_mma<<<dim3(PD/128, RR/128), 256, SMEM_BYTES>>>(0, DD, 0, xr, wir, bi, proj);
    // 5: K2 hid = relu(q @ w1 + b1)            (16 x [4096 x 1024 x 64])  <- ncu -s 5
    gemm_mma<<<dim3(LL/128, RR/128, NHH), 256, SMEM_BYTES>>>(1, DHH, 1, proj, w1t, b1, hid);
    // 6: V^T per batch (from rounded proj)
    transpose_v<<<dim3(32, 32, BSZ), dim3(32, 8)>>>();
    // 7: K3 logits, tri-packed grid (36 tiles x 64 batches)
    gemm_mma<<<dim3(36, 1, NB), 256, SMEM_BYTES>>>(2, LL, 0, hid, w2t, b2, logits);
    // 8: causal softmax in place (rounded probs)
    softmax_causal<<<dim3(LL, NB), 256>>>();
    // 9: PV -> concat layout (tf32 mma)
    gemm_pv_mma<<<dim3(LL/128, NB), 256, PV_SMEM>>>();
    // 10: K6 y = outcat @ Wo^T + bo            (4096 x 1024 x 1024)
    gemm_mma<<<dim3(DD/128, RR/128), 256, SMEM_BYTES>>>(3, DD, 0, outcat, wor, bo, out);
}